// round 5
// baseline (speedup 1.0000x reference)
#include <cuda_runtime.h>
#include <cstdint>
#include <cstddef>

// Problem constants
#define BDIM 4096
#define TDIM 168
#define IDIM 19
#define HDIM 64
#define GDIM 256          // 4*H
#define RPT  7            // rows per rg-group
#define RPC  28           // rows per CTA
#define NCTA 147
#define NT   512

// 704 MB scratch: zx0[t][b][hu][gi]  (layer-0 input projection + biases)
__device__ float g_zx[(size_t)TDIM * BDIM * GDIM];

// ---------------- f32x2 packed-math helpers (sm_100+) ----------------
__device__ __forceinline__ void fma2(unsigned long long& d,
                                     unsigned long long a,
                                     unsigned long long b) {
    asm("fma.rn.f32x2 %0, %1, %2, %0;" : "+l"(d) : "l"(a), "l"(b));
}
__device__ __forceinline__ unsigned long long pack2(float lo, float hi) {
    unsigned long long r;
    asm("mov.b64 %0, {%1, %2};" : "=l"(r) : "f"(lo), "f"(hi));
    return r;
}
__device__ __forceinline__ float redu2(unsigned long long v) {
    float lo, hi;
    asm("mov.b64 {%0, %1}, %2;" : "=f"(lo), "=f"(hi) : "l"(v));
    return lo + hi;
}
__device__ __forceinline__ unsigned long long ld64(const float* p) {
    return *reinterpret_cast<const unsigned long long*>(p);
}

// ---------------- fast activations ----------------
__device__ __forceinline__ float ex2f(float x) {
    float y; asm("ex2.approx.f32 %0, %1;" : "=f"(y) : "f"(x)); return y;
}
__device__ __forceinline__ float rcpf(float x) {
    float y; asm("rcp.approx.f32 %0, %1;" : "=f"(y) : "f"(x)); return y;
}
#define LOG2E 1.4426950408889634f
__device__ __forceinline__ float sigmoidf_(float x) {
    return rcpf(1.0f + ex2f(-x * LOG2E));
}
__device__ __forceinline__ float tanhf_(float x) {
    return 1.0f - 2.0f * rcpf(ex2f(2.0f * LOG2E * x) + 1.0f);
}

// ---------------- named barrier ----------------
__device__ __forceinline__ void barn(int id, int cnt) {
    asm volatile("bar.sync %0, %1;" :: "r"(id), "r"(cnt) : "memory");
}

// =====================================================================
// Prep kernel: g_zx[t][b][hu][gi] = x(b,t,:) . Wih0 + bih0 + bhh0
// =====================================================================
#define TB 4
#define BB 32
#define PNT 256
__global__ void __launch_bounds__(PNT) prep_kernel(
    const float* __restrict__ x,
    const float* __restrict__ Wih0,
    const float* __restrict__ bih0,
    const float* __restrict__ bhh0)
{
    __shared__ __align__(16) float sW[IDIM * GDIM];
    __shared__ float sX[TB][BB][IDIM + 1];
    const int tid = threadIdx.x;
    const int t0 = blockIdx.x * TB;
    const int b0 = blockIdx.y * BB;

    for (int idx = tid; idx < IDIM * GDIM; idx += PNT) {
        int i  = idx >> 8;
        int c  = idx & 255;
        int hh = c >> 2, gi = c & 3;
        sW[idx] = Wih0[(gi * HDIM + hh) * IDIM + i];
    }
    for (int idx = tid; idx < TB * BB * IDIM; idx += PNT) {
        int i  = idx % IDIM;
        int rb = idx / IDIM;
        int bb = rb % BB, tt = rb / BB;
        sX[tt][bb][i] = x[((size_t)(b0 + bb) * TDIM + (t0 + tt)) * IDIM + i];
    }
    __syncthreads();

    const int hh = tid & 63;
    const int sub = tid >> 6;
    float bias[4];
#pragma unroll
    for (int gi = 0; gi < 4; gi++)
        bias[gi] = bih0[gi * HDIM + hh] + bhh0[gi * HDIM + hh];
    const unsigned long long b01 = pack2(bias[0], bias[1]);
    const unsigned long long b23 = pack2(bias[2], bias[3]);

    for (int tt = 0; tt < TB; tt++) {
#pragma unroll
        for (int j = 0; j < BB / 4; j++) {
            const int bb = sub * (BB / 4) + j;
            unsigned long long a01 = b01, a23 = b23;
#pragma unroll
            for (int i = 0; i < IDIM; i++) {
                float xv = sX[tt][bb][i];
                unsigned long long xp = pack2(xv, xv);
                const float* wp = &sW[i * GDIM + hh * 4];
                fma2(a01, xp, ld64(wp));
                fma2(a23, xp, ld64(wp + 2));
            }
            float r0, r1, r2, r3;
            asm("mov.b64 {%0, %1}, %2;" : "=f"(r0), "=f"(r1) : "l"(a01));
            asm("mov.b64 {%0, %1}, %2;" : "=f"(r2), "=f"(r3) : "l"(a23));
            float4 out4 = make_float4(r0, r1, r2, r3);
            *reinterpret_cast<float4*>(
                &g_zx[(((size_t)(t0 + tt) * BDIM + (b0 + bb)) * HDIM + hh) * 4]) = out4;
        }
    }
}

// =====================================================================
// Main recurrent kernel: 147 CTAs x 512 threads (16 warps), GATE-split.
//  kh0 (warps 0-7):  gates {i,f} full-K, owns cell states c0/c1
//  kh1 (warps 8-15): gates {g,o} full-K, writes h
//  Exchange: 7KB smem ping-pong buffer (g down, tanh(c) back)
//  Weights smem layout: sW[kkk][g][4]  -> LDS.128 for both operands
// =====================================================================
__global__ void __launch_bounds__(NT, 1) lstm_kernel(
    const float* __restrict__ Whh0,
    const float* __restrict__ Wih1,
    const float* __restrict__ Whh1,
    const float* __restrict__ bih1,
    const float* __restrict__ bhh1,
    const float* __restrict__ Wfc,
    const float* __restrict__ bfc,
    float* __restrict__ out)
{
    extern __shared__ __align__(16) float smem[];
    float* sW0 = smem;                        // 16*256*4 floats (64 KB)
    float* sW1 = sW0 + 16 * GDIM * 4;         // 32*256*4 floats (128 KB)
    float* h0s = sW1 + 32 * GDIM * 4;         // 28*64
    float* h1s = h0s + RPC * HDIM;            // 28*64
    float* exb = h1s + RPC * HDIM;            // 28*64 exchange (7 KB)

    const int tid  = threadIdx.x;
    const int w    = tid >> 5;                // warp 0..15
    const int kh   = w >> 3;                  // 0: gates i,f | 1: gates g,o
    const int htid = tid & 255;
    const int hu   = htid & 63;
    const int rg   = htid >> 6;               // 0..3
    const int rbase = rg * RPT;
    const size_t growbase = (size_t)blockIdx.x * RPC + rbase;
    const int gbase = kh * 2;                 // first owned gate index

    // ---- stage weights ([kkk][g][4] layout, coalesced float4 reads) ----
    for (int idx = tid; idx < GDIM * 16; idx += NT) {
        int g = idx & 255, kkk = idx >> 8;
        *reinterpret_cast<float4*>(&sW0[(kkk * GDIM + g) * 4]) =
            *reinterpret_cast<const float4*>(&Whh0[g * HDIM + kkk * 4]);
    }
    for (int idx = tid; idx < GDIM * 32; idx += NT) {
        int g = idx & 255, kkk = idx >> 8;
        const float* src = (kkk < 16) ? &Wih1[g * HDIM + kkk * 4]
                                      : &Whh1[g * HDIM + (kkk - 16) * 4];
        *reinterpret_cast<float4*>(&sW1[(kkk * GDIM + g) * 4]) =
            *reinterpret_cast<const float4*>(src);
    }
    for (int idx = tid; idx < RPC * HDIM; idx += NT) {
        h0s[idx] = 0.0f;
        h1s[idx] = 0.0f;
    }
    __syncthreads();

    // L1 bias for my two gates
    const float bA = bih1[(gbase + 0) * HDIM + hu] + bhh1[(gbase + 0) * HDIM + hu];
    const float bB = bih1[(gbase + 1) * HDIM + hu] + bhh1[(gbase + 1) * HDIM + hu];

    float cc0[RPT], cc1[RPT];                 // only meaningful for kh0
#pragma unroll
    for (int r = 0; r < RPT; r++) { cc0[r] = 0.0f; cc1[r] = 0.0f; }

    const int bid = 1 + rg;                   // named barrier id for this rg-group
    float* exg = &exb[rbase * HDIM + hu];     // my 7 exchange slots (stride HDIM)

    // GEMM over one kkk slice: 2 gates x 7 rows, f32x2 pairs via LDS.128
#define GEMM_KKK(SW, HS, KKK, HOFF)                                              \
    do {                                                                         \
        ulonglong2 hv[RPT];                                                      \
        _Pragma("unroll")                                                        \
        for (int r = 0; r < RPT; r++)                                            \
            hv[r] = *reinterpret_cast<const ulonglong2*>(                        \
                &HS[(rbase + r) * HDIM + (HOFF)]);                               \
        ulonglong2 wv0 = *reinterpret_cast<const ulonglong2*>(                   \
            &SW[((KKK) * GDIM + (gbase + 0) * 64 + hu) * 4]);                    \
        ulonglong2 wv1 = *reinterpret_cast<const ulonglong2*>(                   \
            &SW[((KKK) * GDIM + (gbase + 1) * 64 + hu) * 4]);                    \
        _Pragma("unroll")                                                        \
        for (int r = 0; r < RPT; r++) {                                          \
            fma2(accA[r], hv[r].x, wv0.x);                                       \
            fma2(accA[r], hv[r].y, wv0.y);                                       \
            fma2(accB[r], hv[r].x, wv1.x);                                       \
            fma2(accB[r], hv[r].y, wv1.y);                                       \
        }                                                                        \
    } while (0)

    // Pointwise cell-update dance with 3 named barriers.
    // kh0 in: zA=zi, zB=zf ; kh1 in: zA=zg, zB=zo
#define CELL_DANCE(CC, HS)                                                       \
    do {                                                                         \
        if (kh == 0) {                                                           \
            float iv[RPT], fc[RPT];                                              \
            _Pragma("unroll")                                                    \
            for (int r = 0; r < RPT; r++) {                                      \
                iv[r] = sigmoidf_(zA[r]);                                        \
                fc[r] = sigmoidf_(zB[r]) * CC[r];                                \
            }                                                                    \
            barn(bid, 128);  /* g ready */                                       \
            _Pragma("unroll")                                                    \
            for (int r = 0; r < RPT; r++) {                                      \
                float c = fc[r] + iv[r] * exg[r * HDIM];                         \
                CC[r] = c;                                                       \
                exg[r * HDIM] = tanhf_(c);                                       \
            }                                                                    \
            barn(bid, 128);  /* tanh(c) ready */                                 \
            barn(bid, 128);  /* h written */                                     \
        } else {                                                                 \
            float ov[RPT];                                                       \
            _Pragma("unroll")                                                    \
            for (int r = 0; r < RPT; r++) {                                      \
                exg[r * HDIM] = tanhf_(zA[r]);                                   \
                ov[r] = sigmoidf_(zB[r]);                                        \
            }                                                                    \
            barn(bid, 128);  /* g ready */                                       \
            barn(bid, 128);  /* tanh(c) ready */                                 \
            _Pragma("unroll")                                                    \
            for (int r = 0; r < RPT; r++)                                        \
                HS[(rbase + r) * HDIM + hu] = ov[r] * exg[r * HDIM];             \
            barn(bid, 128);  /* h written */                                     \
        }                                                                        \
    } while (0)

    for (int t = 0; t < TDIM; t++) {
        // ================= layer 0 =================
        unsigned long long accA[RPT], accB[RPT];
#pragma unroll
        for (int r = 0; r < RPT; r++) { accA[r] = 0ULL; accB[r] = 0ULL; }

        // prefetch my 2 zx gate columns per row
        float2 zx[RPT];
#pragma unroll
        for (int r = 0; r < RPT; r++) {
            size_t grow = growbase + r;
            zx[r] = (grow < BDIM)
                ? *reinterpret_cast<const float2*>(
                      &g_zx[(((size_t)t * BDIM + grow) * HDIM + hu) * 4 + gbase])
                : make_float2(0.f, 0.f);
        }

#pragma unroll 4
        for (int kkk = 0; kkk < 16; kkk++)
            GEMM_KKK(sW0, h0s, kkk, kkk * 4);

        float zA[RPT], zB[RPT];
#pragma unroll
        for (int r = 0; r < RPT; r++) {
            zA[r] = redu2(accA[r]) + zx[r].x;
            zB[r] = redu2(accB[r]) + zx[r].y;
        }
        CELL_DANCE(cc0, h0s);

        // ================= layer 1 (K = 128: [h0_new ; h1_old]) =================
#pragma unroll
        for (int r = 0; r < RPT; r++) { accA[r] = 0ULL; accB[r] = 0ULL; }
#pragma unroll 4
        for (int kkk = 0; kkk < 16; kkk++)
            GEMM_KKK(sW1, h0s, kkk, kkk * 4);
#pragma unroll 4
        for (int kkk = 16; kkk < 32; kkk++)
            GEMM_KKK(sW1, h1s, kkk, (kkk - 16) * 4);

#pragma unroll
        for (int r = 0; r < RPT; r++) {
            zA[r] = redu2(accA[r]) + bA;
            zB[r] = redu2(accB[r]) + bB;
        }
        CELL_DANCE(cc1, h1s);
    }

    __syncthreads();

    // ---- final FC on last hidden state ----
    if (tid < RPC) {
        size_t grow = (size_t)blockIdx.x * RPC + tid;
        if (grow < BDIM) {
            float s = bfc[0];
#pragma unroll 8
            for (int k = 0; k < HDIM; k++) s += h1s[tid * HDIM + k] * Wfc[k];
            out[grow] = s;
        }
    }
}

// =====================================================================
extern "C" void kernel_launch(void* const* d_in, const int* in_sizes, int n_in,
                              void* d_out, int out_size)
{
    const float* x    = (const float*)d_in[0];
    const float* Wih0 = (const float*)d_in[1];
    const float* Whh0 = (const float*)d_in[2];
    const float* bih0 = (const float*)d_in[3];
    const float* bhh0 = (const float*)d_in[4];
    const float* Wih1 = (const float*)d_in[5];
    const float* Whh1 = (const float*)d_in[6];
    const float* bih1 = (const float*)d_in[7];
    const float* bhh1 = (const float*)d_in[8];
    const float* Wfc  = (const float*)d_in[9];
    const float* bfc  = (const float*)d_in[10];
    float* out = (float*)d_out;

    const int smem_bytes = (16 * GDIM * 4 + 32 * GDIM * 4 + 3 * RPC * HDIM) * 4;
    cudaFuncSetAttribute(lstm_kernel,
                         cudaFuncAttributeMaxDynamicSharedMemorySize, smem_bytes);

    dim3 pgrid(TDIM / TB, BDIM / BB);
    prep_kernel<<<pgrid, PNT>>>(x, Wih0, bih0, bhh0);
    lstm_kernel<<<NCTA, NT, smem_bytes>>>(Whh0, Wih1, Whh1, bih1, bhh1,
                                          Wfc, bfc, out);
}

// round 6
// speedup vs baseline: 1.7541x; 1.7541x over previous
#include <cuda_runtime.h>
#include <cstdint>
#include <cstddef>

// Problem constants
#define BDIM 4096
#define TDIM 168
#define IDIM 19
#define HDIM 64
#define GDIM 256          // 4*H
#define RPT  7            // rows per rg-group
#define RPC  28           // rows per CTA
#define NCTA 147
#define NT   256

// 704 MB scratch: zx0[t][b][hu][gi]  (layer-0 input projection + biases)
__device__ float g_zx[(size_t)TDIM * BDIM * GDIM];

// ---------------- f32x2 packed-math helpers (sm_100+) ----------------
__device__ __forceinline__ void fma2(unsigned long long& d,
                                     unsigned long long a,
                                     unsigned long long b) {
    asm("fma.rn.f32x2 %0, %1, %2, %0;" : "+l"(d) : "l"(a), "l"(b));
}
__device__ __forceinline__ unsigned long long pack2(float lo, float hi) {
    unsigned long long r;
    asm("mov.b64 %0, {%1, %2};" : "=l"(r) : "f"(lo), "f"(hi));
    return r;
}
__device__ __forceinline__ float redu2(unsigned long long v) {
    float lo, hi;
    asm("mov.b64 {%0, %1}, %2;" : "=f"(lo), "=f"(hi) : "l"(v));
    return lo + hi;
}
__device__ __forceinline__ unsigned long long ld64(const float* p) {
    return *reinterpret_cast<const unsigned long long*>(p);
}

// ---------------- fast activations ----------------
__device__ __forceinline__ float ex2f(float x) {
    float y; asm("ex2.approx.f32 %0, %1;" : "=f"(y) : "f"(x)); return y;
}
__device__ __forceinline__ float rcpf(float x) {
    float y; asm("rcp.approx.f32 %0, %1;" : "=f"(y) : "f"(x)); return y;
}
#define LOG2E 1.4426950408889634f
__device__ __forceinline__ float sigmoidf_(float x) {
    return rcpf(1.0f + ex2f(-x * LOG2E));
}
__device__ __forceinline__ float tanhf_(float x) {
    return 1.0f - 2.0f * rcpf(ex2f(2.0f * LOG2E * x) + 1.0f);
}

// ---------------- named barrier ----------------
__device__ __forceinline__ void barn(int id, int cnt) {
    asm volatile("bar.sync %0, %1;" :: "r"(id), "r"(cnt) : "memory");
}

// =====================================================================
// Prep kernel: g_zx[t][b][hu][gi] = x(b,t,:) . Wih0 + bih0 + bhh0
// =====================================================================
#define TB 4
#define BB 32
#define PNT 256
__global__ void __launch_bounds__(PNT) prep_kernel(
    const float* __restrict__ x,
    const float* __restrict__ Wih0,
    const float* __restrict__ bih0,
    const float* __restrict__ bhh0)
{
    __shared__ __align__(16) float sW[IDIM * GDIM];
    __shared__ float sX[TB][BB][IDIM + 1];
    const int tid = threadIdx.x;
    const int t0 = blockIdx.x * TB;
    const int b0 = blockIdx.y * BB;

    for (int idx = tid; idx < IDIM * GDIM; idx += PNT) {
        int i  = idx >> 8;
        int c  = idx & 255;
        int hh = c >> 2, gi = c & 3;
        sW[idx] = Wih0[(gi * HDIM + hh) * IDIM + i];
    }
    for (int idx = tid; idx < TB * BB * IDIM; idx += PNT) {
        int i  = idx % IDIM;
        int rb = idx / IDIM;
        int bb = rb % BB, tt = rb / BB;
        sX[tt][bb][i] = x[((size_t)(b0 + bb) * TDIM + (t0 + tt)) * IDIM + i];
    }
    __syncthreads();

    const int hh = tid & 63;
    const int sub = tid >> 6;
    float bias[4];
#pragma unroll
    for (int gi = 0; gi < 4; gi++)
        bias[gi] = bih0[gi * HDIM + hh] + bhh0[gi * HDIM + hh];
    const unsigned long long b01 = pack2(bias[0], bias[1]);
    const unsigned long long b23 = pack2(bias[2], bias[3]);

    for (int tt = 0; tt < TB; tt++) {
#pragma unroll
        for (int j = 0; j < BB / 4; j++) {
            const int bb = sub * (BB / 4) + j;
            unsigned long long a01 = b01, a23 = b23;
#pragma unroll
            for (int i = 0; i < IDIM; i++) {
                float xv = sX[tt][bb][i];
                unsigned long long xp = pack2(xv, xv);
                const float* wp = &sW[i * GDIM + hh * 4];
                fma2(a01, xp, ld64(wp));
                fma2(a23, xp, ld64(wp + 2));
            }
            float r0, r1, r2, r3;
            asm("mov.b64 {%0, %1}, %2;" : "=f"(r0), "=f"(r1) : "l"(a01));
            asm("mov.b64 {%0, %1}, %2;" : "=f"(r2), "=f"(r3) : "l"(a23));
            float4 out4 = make_float4(r0, r1, r2, r3);
            *reinterpret_cast<float4*>(
                &g_zx[(((size_t)(t0 + tt) * BDIM + (b0 + bb)) * HDIM + hh) * 4]) = out4;
        }
    }
}

// =====================================================================
// Main recurrent kernel: 147 CTAs x 256 threads, 28 rows per CTA.
// Thread: hu = tid&63, rg = tid>>6; 7 rows x 4 gates per thread.
// Key changes vs R1:
//  - ALL data flow is rg-group-local (64 threads = 2 warps): use 64-thread
//    named barriers instead of __syncthreads. Groups on each SMSP de-phase,
//    so one warp's MUFU/activation phase hides under the other's FMA phase.
//  - Double-buffered h0/h1 -> only 2 barriers per timestep.
//  - Weights in [kkk][g][4] layout: LDS.128 for both operands
//    (crossbar 11520 -> 8832 SM-cyc/step, below the FMA floor).
// =====================================================================
__global__ void __launch_bounds__(NT, 1) lstm_kernel(
    const float* __restrict__ Whh0,
    const float* __restrict__ Wih1,
    const float* __restrict__ Whh1,
    const float* __restrict__ bih1,
    const float* __restrict__ bhh1,
    const float* __restrict__ Wfc,
    const float* __restrict__ bfc,
    float* __restrict__ out)
{
    extern __shared__ __align__(16) float smem[];
    float* sW0 = smem;                         // 16*256*4 = 16384 floats (64 KB)
    float* sW1 = sW0 + 16 * GDIM * 4;          // 32*256*4 = 32768 floats (128 KB)
    float* h0a = sW1 + 32 * GDIM * 4;          // 28*64
    float* h0b = h0a + RPC * HDIM;
    float* h1a = h0b + RPC * HDIM;
    float* h1b = h1a + RPC * HDIM;

    const int tid = threadIdx.x;
    const int hu  = tid & 63;
    const int rg  = tid >> 6;                  // 0..3
    const int rbase = rg * RPT;
    const size_t growbase = (size_t)blockIdx.x * RPC + rbase;
    const int bid = 1 + rg;                    // named barrier per rg-group

    // ---- stage weights in [kkk][g][4] layout (coalesced float4 gmem reads) ----
    for (int idx = tid; idx < GDIM * 16; idx += NT) {
        int g = idx & 255, kkk = idx >> 8;
        *reinterpret_cast<float4*>(&sW0[(kkk * GDIM + g) * 4]) =
            *reinterpret_cast<const float4*>(&Whh0[g * HDIM + kkk * 4]);
    }
    for (int idx = tid; idx < GDIM * 32; idx += NT) {
        int g = idx & 255, kkk = idx >> 8;
        const float* src = (kkk < 16) ? &Wih1[g * HDIM + kkk * 4]
                                      : &Whh1[g * HDIM + (kkk - 16) * 4];
        *reinterpret_cast<float4*>(&sW1[(kkk * GDIM + g) * 4]) =
            *reinterpret_cast<const float4*>(src);
    }
    for (int idx = tid; idx < RPC * HDIM; idx += NT) {
        h0a[idx] = 0.0f; h0b[idx] = 0.0f;
        h1a[idx] = 0.0f; h1b[idx] = 0.0f;
    }

    float b1v[4];
#pragma unroll
    for (int gi = 0; gi < 4; gi++)
        b1v[gi] = bih1[gi * HDIM + hu] + bhh1[gi * HDIM + hu];

    float c0[RPT], c1[RPT];
#pragma unroll
    for (int r = 0; r < RPT; r++) { c0[r] = 0.0f; c1[r] = 0.0f; }

    __syncthreads();   // weights + initial h visible to all

    // GEMM over one kkk slice (4 consecutive k): 4 gates x 7 rows,
    // both operands via LDS.128.
#define GEMM_KKK(SW, HS, KKK, HOFF)                                              \
    do {                                                                         \
        ulonglong2 hv[RPT];                                                      \
        _Pragma("unroll")                                                        \
        for (int r = 0; r < RPT; r++)                                            \
            hv[r] = *reinterpret_cast<const ulonglong2*>(                        \
                &HS[(rbase + r) * HDIM + (HOFF)]);                               \
        _Pragma("unroll")                                                        \
        for (int gi = 0; gi < 4; gi++) {                                         \
            ulonglong2 wv = *reinterpret_cast<const ulonglong2*>(                \
                &SW[((KKK) * GDIM + gi * 64 + hu) * 4]);                         \
            _Pragma("unroll")                                                    \
            for (int r = 0; r < RPT; r++) {                                      \
                fma2(acc[r][gi], hv[r].x, wv.x);                                 \
                fma2(acc[r][gi], hv[r].y, wv.y);                                 \
            }                                                                    \
        }                                                                        \
    } while (0)

    float* h0r = h0a; float* h0w = h0b;
    float* h1r = h1a; float* h1w = h1b;

    for (int t = 0; t < TDIM; t++) {
        unsigned long long acc[RPT][4];

        // ================= layer 0 =================
        float4 zx[RPT];
#pragma unroll
        for (int r = 0; r < RPT; r++) {
            size_t grow = growbase + r;
            zx[r] = (grow < BDIM)
                ? *reinterpret_cast<const float4*>(
                      &g_zx[(((size_t)t * BDIM + grow) * HDIM + hu) * 4])
                : make_float4(0.f, 0.f, 0.f, 0.f);
        }

#pragma unroll
        for (int r = 0; r < RPT; r++)
#pragma unroll
            for (int gi = 0; gi < 4; gi++) acc[r][gi] = 0ULL;
#pragma unroll 2
        for (int kkk = 0; kkk < 16; kkk++)
            GEMM_KKK(sW0, h0r, kkk, kkk * 4);

#pragma unroll
        for (int r = 0; r < RPT; r++) {
            float zi = redu2(acc[r][0]) + zx[r].x;
            float zf = redu2(acc[r][1]) + zx[r].y;
            float zg = redu2(acc[r][2]) + zx[r].z;
            float zo = redu2(acc[r][3]) + zx[r].w;
            float ig = sigmoidf_(zi);
            float fg = sigmoidf_(zf);
            float gg = tanhf_(zg);
            float og = sigmoidf_(zo);
            float c = fg * c0[r] + ig * gg;
            c0[r] = c;
            h0w[(rbase + r) * HDIM + hu] = og * tanhf_(c);
        }
        barn(bid, 64);       // group-local: h0w visible (write buffer != read)

        // ================= layer 1 (K=128: [h0_new ; h1_old]) =================
#pragma unroll
        for (int r = 0; r < RPT; r++)
#pragma unroll
            for (int gi = 0; gi < 4; gi++) acc[r][gi] = 0ULL;
#pragma unroll 2
        for (int kkk = 0; kkk < 16; kkk++)
            GEMM_KKK(sW1, h0w, kkk, kkk * 4);
#pragma unroll 2
        for (int kkk = 16; kkk < 32; kkk++)
            GEMM_KKK(sW1, h1r, kkk, (kkk - 16) * 4);

#pragma unroll
        for (int r = 0; r < RPT; r++) {
            float zi = redu2(acc[r][0]) + b1v[0];
            float zf = redu2(acc[r][1]) + b1v[1];
            float zg = redu2(acc[r][2]) + b1v[2];
            float zo = redu2(acc[r][3]) + b1v[3];
            float ig = sigmoidf_(zi);
            float fg = sigmoidf_(zf);
            float gg = tanhf_(zg);
            float og = sigmoidf_(zo);
            float c = fg * c1[r] + ig * gg;
            c1[r] = c;
            h1w[(rbase + r) * HDIM + hu] = og * tanhf_(c);
        }
        barn(bid, 64);       // group-local: h1w visible; safe to swap

        // swap double buffers
        float* tp;
        tp = h0r; h0r = h0w; h0w = tp;
        tp = h1r; h1r = h1w; h1w = tp;
    }

    __syncthreads();

    // ---- final FC on last hidden state (h1r holds the last write) ----
    if (tid < RPC) {
        size_t grow = (size_t)blockIdx.x * RPC + tid;
        if (grow < BDIM) {
            float s = bfc[0];
#pragma unroll 8
            for (int k = 0; k < HDIM; k++) s += h1r[tid * HDIM + k] * Wfc[k];
            out[grow] = s;
        }
    }
}

// =====================================================================
extern "C" void kernel_launch(void* const* d_in, const int* in_sizes, int n_in,
                              void* d_out, int out_size)
{
    const float* x    = (const float*)d_in[0];
    const float* Wih0 = (const float*)d_in[1];
    const float* Whh0 = (const float*)d_in[2];
    const float* bih0 = (const float*)d_in[3];
    const float* bhh0 = (const float*)d_in[4];
    const float* Wih1 = (const float*)d_in[5];
    const float* Whh1 = (const float*)d_in[6];
    const float* bih1 = (const float*)d_in[7];
    const float* bhh1 = (const float*)d_in[8];
    const float* Wfc  = (const float*)d_in[9];
    const float* bfc  = (const float*)d_in[10];
    float* out = (float*)d_out;

    const int smem_bytes = (16 * GDIM * 4 + 32 * GDIM * 4 + 4 * RPC * HDIM) * 4;
    cudaFuncSetAttribute(lstm_kernel,
                         cudaFuncAttributeMaxDynamicSharedMemorySize, smem_bytes);

    dim3 pgrid(TDIM / TB, BDIM / BB);
    prep_kernel<<<pgrid, PNT>>>(x, Wih0, bih0, bhh0);
    lstm_kernel<<<NCTA, NT, smem_bytes>>>(Whh0, Wih1, Whh1, bih1, bhh1,
                                          Wfc, bfc, out);
}